// round 9
// baseline (speedup 1.0000x reference)
#include <cuda_runtime.h>
#include <cstdint>

#define BT20   2621440u     // B*20 (elements per head slab)
#define HALFN  52428800u    // 20*BT20
#define TPB    64

// ---- packed f32x2 helpers ----
__device__ __forceinline__ unsigned long long pack2(float lo, float hi) {
    unsigned long long r;
    asm("mov.b64 %0, {%1, %2};" : "=l"(r) : "f"(lo), "f"(hi));
    return r;
}
__device__ __forceinline__ void unpack2(unsigned long long v, float &lo, float &hi) {
    asm("mov.b64 {%0, %1}, %2;" : "=f"(lo), "=f"(hi) : "l"(v));
}
__device__ __forceinline__ void fma2(unsigned long long &d, unsigned long long a,
                                     unsigned long long b) {
    asm("fma.rn.f32x2 %0, %1, %2, %0;" : "+l"(d) : "l"(a), "l"(b));
}
__device__ __forceinline__ void add2(unsigned long long &d, unsigned long long a) {
    asm("add.rn.f32x2 %0, %0, %1;" : "+l"(d) : "l"(a));
}
__device__ __forceinline__ unsigned long long f2lo(const float4 &v) { return pack2(v.x, v.y); }
__device__ __forceinline__ unsigned long long f2hi(const float4 &v) { return pack2(v.z, v.w); }

// integer add on the FMA pipe (IMAD); 'one' is runtime-opaque
__device__ __forceinline__ uint32_t addm(uint32_t a, uint32_t b, uint32_t one) {
    uint32_t r;
    asm("mad.lo.u32 %0, %1, %2, %3;" : "=r"(r) : "r"(b), "r"(one), "r"(a));
    return r;
}

// ---- Threefry-2x32-20, key (0,42); returns ~(o0^o1); keep-bit in MSB ----
// (verified bit-exact vs JAX partitionable threefry in earlier rounds)
__device__ __forceinline__ uint32_t tf_mix(uint32_t x1_init, uint32_t one) {
    const uint32_t ks1 = 42u;
    const uint32_t ks2 = 0x1BD11BDAu ^ 42u;
    uint32_t x1 = x1_init;          // c1 + ks1
    uint32_t x0 = x1;               // round 1 add with x0=0
    x1 = __funnelshift_l(x1, x1, 13) ^ x0;
#define TF_R(r)  { x0 = addm(x0, x1, one); \
                   x1 = __funnelshift_l(x1, x1, (r)); x1 ^= x0; }
    TF_R(15) TF_R(26) TF_R(6)
    x0 += ks1;  x1 += ks2 + 1u;
    TF_R(17) TF_R(29) TF_R(16) TF_R(24)
    x0 += ks2;  x1 += 2u;
    TF_R(13) TF_R(15) TF_R(26) TF_R(6)
    x1 += ks1 + 3u;
    TF_R(17) TF_R(29) TF_R(16) TF_R(24)
    x0 += ks1;  x1 += ks2 + 4u;
    TF_R(13) TF_R(15) TF_R(26) TF_R(6)
    x0 += ks2;  x1 += 5u;
#undef TF_R
    return ~(x0 ^ x1);
}

// keep-multiplier 2.0f / 0.0f from mask bit o
__device__ __forceinline__ float keepf(uint32_t m, int o) {
    return __uint_as_float((uint32_t)((int)(m << (31 - o)) >> 31) & 0x40000000u);
}

// ============ fused kernel, split-d: 2 lanes per row (lane ^ 16 pairs) ======
__global__ __launch_bounds__(TPB, 10)
void fused_kernel(const float* __restrict__ x,
                  const float* __restrict__ W1,
                  const float* __restrict__ b1,
                  const float* __restrict__ Wh,
                  const float* __restrict__ bh,
                  float* __restrict__ out,
                  uint32_t one)
{
    __shared__ __align__(16) float sW1p[64 * 20];  // rows 60..63 zero
    __shared__           float sb1p[64];           // 60..63 zero
    __shared__ __align__(16) float sbh[800];       // [40][20]
    __shared__ __align__(16) float sWhA[20 * 64];  // Wh[k],    rows padded to 64
    __shared__ __align__(16) float sWhB[20 * 64];  // Wh[k+20], rows padded to 64

    const int tid = threadIdx.x;

    // constants + zero pads
    for (int i = tid; i < 300; i += TPB)
        ((float4*)sW1p)[i] = ((const float4*)W1)[i];
    for (int i = tid; i < 200; i += TPB)
        ((float4*)sbh)[i] = ((const float4*)bh)[i];
    if (tid < 20) {                                   // sW1p rows 60..63 = 0
        ((float4*)sW1p)[300 + tid] = make_float4(0.f, 0.f, 0.f, 0.f);
        ((float4*)sWhA)[tid * 16 + 15] = make_float4(0.f, 0.f, 0.f, 0.f);
        ((float4*)sWhB)[tid * 16 + 15] = make_float4(0.f, 0.f, 0.f, 0.f);
    }
    if (tid < 64) sb1p[tid] = (tid < 60) ? b1[tid] : 0.f;
    __syncthreads();

    const unsigned lane = (unsigned)tid & 31u;
    const unsigned warp = (unsigned)tid >> 5;
    const unsigned half = lane >> 4;                 // 0: d 0..31, 1: d 32..63
    const unsigned row  = blockIdx.x * 32u + warp * 16u + (lane & 15u);
    const unsigned base_b = row * 20u;

    // ---- trunk: this lane computes h components [half*32, half*32+32) ----
    unsigned long long h2h[16];
    {
        unsigned long long x2[10];
        const float4* xp = (const float4*)(x + (size_t)row * 20);
        #pragma unroll
        for (int i = 0; i < 5; i++) {
            float4 v = xp[i];
            x2[2*i]   = f2lo(v);
            x2[2*i+1] = f2hi(v);
        }
        const unsigned cbase = half * 32u;
        #pragma unroll
        for (int i = 0; i < 16; i++) {
            unsigned long long a0 = 0ull, a1 = 0ull, a2 = 0ull, a3 = 0ull;
            const float4* w0 = (const float4*)(sW1p + (cbase + 2*i) * 20);
            const float4* w1 = w0 + 5;               // next row (+20 floats)
            #pragma unroll
            for (int d = 0; d < 5; d++) {
                float4 v0 = w0[d], v1 = w1[d];
                fma2(a0, x2[2*d],   f2lo(v0));
                fma2(a2, x2[2*d+1], f2hi(v0));
                fma2(a1, x2[2*d],   f2lo(v1));
                fma2(a3, x2[2*d+1], f2hi(v1));
            }
            add2(a0, a2);
            add2(a1, a3);
            float s0a, s0b, s1a, s1b;
            unpack2(a0, s0a, s0b);
            unpack2(a1, s1a, s1b);
            h2h[i] = pack2(fmaxf(s0a + s0b + sb1p[cbase + 2*i],   0.f),
                           fmaxf(s1a + s1b + sb1p[cbase + 2*i+1], 0.f));
        }
    }

    // ---- prologue mask (k = 0): this lane's head = 20*half ----
    uint32_t m = 0u;
    {
        const uint32_t j0 = half * HALFN + base_b + 42u;
        #pragma unroll
        for (int o = 0; o < 20; o++)
            m |= (tf_mix(j0 + (unsigned)o, one) >> 31) << o;
    }

    for (int k = 0; k < 20; k++) {
        __syncthreads();   // protect previous iteration's sWh reads
        const float4* srcA = (const float4*)(Wh + (size_t)k        * 1200);
        const float4* srcB = (const float4*)(Wh + (size_t)(k + 20) * 1200);
        for (int i = tid; i < 300; i += TPB) {
            int r_ = i / 15, c4 = i % 15;
            int d4 = r_ * 16 + c4;                   // padded row-64 layout
            ((float4*)sWhA)[d4] = srcA[i];
            ((float4*)sWhB)[d4] = srcB[i];
        }
        __syncthreads();

        uint32_t nm = 0u;
        const uint32_t nbase = (unsigned)(k + 1) * BT20 + half * HALFN + base_b + 42u;

        #pragma unroll 1
        for (int oc = 0; oc < 5; oc++) {
            float yv[4];
            #pragma unroll
            for (int u = 0; u < 4; u++) {
                const int o = oc * 4 + u;
                const float4* wA = (const float4*)(sWhA + o * 64 + half * 32);
                const float4* wB = (const float4*)(sWhB + o * 64 + half * 32);
                unsigned long long a0 = 0ull, a1 = 0ull, c0 = 0ull, c1 = 0ull;
                #pragma unroll
                for (int d = 0; d < 8; d++) {
                    float4 va = wA[d];
                    float4 vb = wB[d];
                    fma2(a0, f2lo(va), h2h[2*d]);
                    fma2(a1, f2hi(va), h2h[2*d+1]);
                    fma2(c0, f2lo(vb), h2h[2*d]);
                    fma2(c1, f2hi(vb), h2h[2*d+1]);
                }
                add2(a0, a1);
                add2(c0, c1);
                float p, q;
                unpack2(a0, p, q);
                float pa = p + q;                     // half-dot, head A
                unpack2(c0, p, q);
                float pb = p + q;                     // half-dot, head B
                pa += __shfl_xor_sync(0xffffffffu, pa, 16);
                pb += __shfl_xor_sync(0xffffffffu, pb, 16);
                const float tot  = half ? pb : pa;    // this lane's head
                const float bias = sbh[(k + 20 * (int)half) * 20 + o];
                yv[u] = fmaxf(tot + bias, 0.f) * keepf(m, o);

                // one threefry block for next-k mask (fills stall slots)
                nm |= (tf_mix(nbase + (unsigned)o, one) >> 31) << o;
            }
            *(float4*)(out + (size_t)(k + 20 * (int)half) * BT20 + base_b + oc * 4) =
                make_float4(yv[0], yv[1], yv[2], yv[3]);
        }
        m = nm;
    }
}

extern "C" void kernel_launch(void* const* d_in, const int* in_sizes, int n_in,
                              void* d_out, int out_size) {
    const float* x  = (const float*)d_in[0];   // [131072, 20]
    const float* W1 = (const float*)d_in[1];   // [60, 20]
    const float* b1 = (const float*)d_in[2];   // [60]
    const float* Wh = (const float*)d_in[3];   // [40, 20, 60]
    const float* bh = (const float*)d_in[4];   // [40, 20]
    float* out = (float*)d_out;                // [40, 131072, 1, 20]

    const int rows = in_sizes[0] / 20;         // 131072
    fused_kernel<<<rows / 32, TPB>>>(x, W1, b1, Wh, bh, out, 1u);
}